// round 13
// baseline (speedup 1.0000x reference)
#include <cuda_runtime.h>
#include <cuda_fp16.h>
#include <math_constants.h>
#include <cstdint>

// ============================================================================
// ContrastiveLoss: S = txt @ img^T once via single-pass fp16 mma.sync.
// Row-LSE (t2i) + Col-LSE (i2t) fused into GEMM epilogue (branch-free
// two-pass, R11: 49.6us). R13: (a) tail reverted to R11 (R12 fusion lost
// 1.6us), (b) convert_h 2x threads (latency-bound at issue=8%),
// (c) PERSISTENT gemm CTAs: grid=296, ~3.5 tiles/CTA, cp.async pipeline runs
// continuously across tile boundaries (no per-tile fill/drain).
// ============================================================================

#define B_DIM 4096
#define D_DIM 256
#define MARGIN 0.2f
#define INV_L  100.0f
#define SWZ(x) ((x) ^ (((x) >> 3) & 0x70))

#define NCTA 296            // 148 SMs x 2 CTAs
#define NTILES 1024         // 32 x 32 tiles of 128x128

__device__ __align__(16) __half g_txt_h[B_DIM * D_DIM];
__device__ __align__(16) __half g_img_h[B_DIM * D_DIM];
__device__ float2 g_rowp[B_DIM * 32];     // (row, ntile)
__device__ float2 g_colp[B_DIM * 32];     // (col, mtile)
__device__ float  g_pos[B_DIM];
__device__ float  g_loss[2 * B_DIM];

// ---- PTX helpers (sm_80-portable only) ----
__device__ __forceinline__ uint32_t smem_u32(const void* p) {
    uint32_t a;
    asm("{ .reg .u64 t; cvta.to.shared.u64 t, %1; cvt.u32.u64 %0, t; }" : "=r"(a) : "l"(p));
    return a;
}
__device__ __forceinline__ void cpa16(uint32_t dst, const void* src) {
    asm volatile("cp.async.cg.shared.global [%0], [%1], 16;" :: "r"(dst), "l"(src));
}
#define CP_COMMIT() asm volatile("cp.async.commit_group;" ::: "memory")
#define CP_WAIT(n)  asm volatile("cp.async.wait_group %0;" :: "n"(n) : "memory")

__device__ __forceinline__ void ldm4(uint32_t* r, uint32_t addr) {
    asm volatile("ldmatrix.sync.aligned.m8n8.x4.shared.b16 {%0,%1,%2,%3}, [%4];"
                 : "=r"(r[0]), "=r"(r[1]), "=r"(r[2]), "=r"(r[3]) : "r"(addr));
}
__device__ __forceinline__ void mma_f16(float* c, const uint32_t* a, uint32_t b0, uint32_t b1) {
    asm volatile("mma.sync.aligned.m16n8k16.row.col.f32.f16.f16.f32 "
                 "{%0,%1,%2,%3}, {%4,%5,%6,%7}, {%8,%9}, {%0,%1,%2,%3};"
                 : "+f"(c[0]), "+f"(c[1]), "+f"(c[2]), "+f"(c[3])
                 : "r"(a[0]), "r"(a[1]), "r"(a[2]), "r"(a[3]), "r"(b0), "r"(b1));
}

__device__ __forceinline__ void lse_merge(float& m, float& s, float m2, float s2) {
    if (m2 > m) { s = s * __expf((m - m2) * INV_L) + s2; m = m2; }
    else if (s2 > 0.f) s += s2 * __expf((m2 - m) * INV_L);
}
__device__ __forceinline__ float finish_loss(float m, float s, float pos) {
    float M = fmaxf(m, pos);
    float tot = __expf((pos - M) * INV_L) + s * __expf((m - M) * INV_L);
    return (M - pos) * INV_L + logf(tot);
}

// ---------------------------------------------------------------------------
// Convert fp32 -> fp16 plane. 1 thread = 4 elements (2x threads vs R11:
// kernel was latency-bound at issue=8%).
// ---------------------------------------------------------------------------
__global__ void __launch_bounds__(256) convert_h(const float* __restrict__ img,
                                                 const float* __restrict__ txt) {
    const float* src = (blockIdx.y == 0) ? img : txt;
    char* dst = (char*)((blockIdx.y == 0) ? g_img_h : g_txt_h);
    int idx = blockIdx.x * 256 + threadIdx.x;          // 0..262143
    size_t e0 = (size_t)idx * 4;
    float4 a = *(const float4*)(src + e0);
    union { __half h[4]; uint2 u; } H;
    H.h[0] = __float2half_rn(a.x);
    H.h[1] = __float2half_rn(a.y);
    H.h[2] = __float2half_rn(a.z);
    H.h[3] = __float2half_rn(a.w);
    *(uint2*)(dst + e0 * 2) = H.u;
}

// ---------------------------------------------------------------------------
// Persistent GEMM + fused row/col LSE. CTA tile 128x128, 8 warps = 4Mx2N,
// warp tile 32x64. Flat chunk stream (8 K-chunks of 32 per tile), 4-stage
// cp.async pipeline continuous across tiles. Stages 64KB + partials 6KB.
// ---------------------------------------------------------------------------
#define STAGE 16384
#define A_OFF 0
#define B_OFF 8192
#define PART_OFF (4 * STAGE)
#define SMEM_TOTAL (4 * STAGE + 6144 + 1024)

__device__ __forceinline__ void load_chunk(uint32_t buf, int tile, int s, int tid) {
    const int m0 = (tile >> 5) * 128, n0 = (tile & 31) * 128;
    const char* At = (const char*)g_txt_h;
    const char* Bi = (const char*)g_img_h;
#pragma unroll
    for (int it = 0; it < 2; it++) {
        int idx = it * 256 + tid;
        int r = idx >> 2, u = idx & 3;
        uint32_t off = (uint32_t)(r * 64 + u * 16);
        cpa16(buf + A_OFF + SWZ(off), At + (size_t)(m0 + r) * 512 + s * 64 + u * 16);
        cpa16(buf + B_OFF + SWZ(off), Bi + (size_t)(n0 + r) * 512 + s * 64 + u * 16);
    }
    CP_COMMIT();
}

__global__ void __launch_bounds__(256, 2) gemm_lse() {
    extern __shared__ char smem[];
    const uint32_t smem_raw = smem_u32(smem);
    const uint32_t sb = (smem_raw + 1023) & ~1023u;
    char* pbase = smem + (sb - smem_raw) + PART_OFF;
    float2* rowp = (float2*)pbase;              // [128][2]
    float2* colp = (float2*)(pbase + 2048);     // [128][4]

    const int tid = threadIdx.x, lane = tid & 31, wid = tid >> 5;
    const int warp_m = wid & 3, warp_n = wid >> 2;
    const int cta = blockIdx.x;
    const int myT = (NTILES - 1 - cta) / NCTA + 1;      // 4 for cta<136 else 3

    const int a_row = warp_m * 32 + (lane & 15);
    const int a_kb  = (lane >> 4) << 4;
    const int b_row = warp_n * 64 + (lane & 7) + ((lane >> 4) << 3);
    const int b_kb  = ((lane >> 3) & 1) << 4;
    const int gID = lane >> 2, tig = lane & 3;

    float c[2][8][4];
#pragma unroll
    for (int i = 0; i < 2; i++)
#pragma unroll
        for (int j = 0; j < 8; j++)
#pragma unroll
            for (int k = 0; k < 4; k++) c[i][j][k] = 0.f;

    // prologue: chunks 0..2 of first tile (myT >= 3 always => all in tile 0)
#pragma unroll
    for (int s = 0; s < 3; s++)
        load_chunk(sb + s * STAGE, cta, s, tid);

    for (int t = 0; t < myT; t++) {
        const int tile = cta + NCTA * t;
        const bool last = (t == myT - 1);
#pragma unroll
        for (int s = 0; s < 8; s++) {
            // group g = t*8+s completes when pending <= 2 (earlier commits
            // exist), except near stream end on the last tile.
            if (!last || s <= 5) CP_WAIT(2);
            else if (s == 6) CP_WAIT(1);
            else CP_WAIT(0);
            __syncthreads();

            if (!last || s < 5) {               // chunk g+3 exists
                const int ns = s + 3;
                const int ntl = t + (ns >> 3);
                load_chunk(sb + (((t * 8 + ns) & 3)) * STAGE,
                           cta + NCTA * ntl, ns & 7, tid);
            }

            const uint32_t bb = sb + ((t * 8 + s) & 3) * STAGE;
#pragma unroll
            for (int ks = 0; ks < 2; ks++) {
                const int kb = ks * 32;
                uint32_t ah[2][4];
#pragma unroll
                for (int mi = 0; mi < 2; mi++)
                    ldm4(ah[mi], bb + A_OFF + SWZ((uint32_t)((a_row + mi * 16) * 64 + kb + a_kb)));
                uint32_t bh[4][4];
#pragma unroll
                for (int p = 0; p < 4; p++)
                    ldm4(bh[p], bb + B_OFF + SWZ((uint32_t)((b_row + p * 16) * 64 + kb + b_kb)));
#pragma unroll
                for (int mi = 0; mi < 2; mi++)
#pragma unroll
                    for (int p = 0; p < 4; p++)
#pragma unroll
                        for (int h = 0; h < 2; h++)
                            mma_f16(c[mi][p * 2 + h], ah[mi], bh[p][h * 2], bh[p][h * 2 + 1]);
            }
        }

        // ---- per-tile epilogue: branch-free two-pass LSE ----
        const int mtile = tile >> 5, ntile = tile & 31;
        const int m0 = mtile * 128, n0 = ntile * 128;
        const int mb = m0 + warp_m * 32;
        const int nb = n0 + warp_n * 64;

        // rows (t2i)
#pragma unroll
        for (int mi = 0; mi < 2; mi++)
#pragma unroll
            for (int r = 0; r < 2; r++) {
                const int m = mb + mi * 16 + gID + 8 * r;
                float mm = -CUDART_INF_F;
#pragma unroll
                for (int q = 0; q < 8; q++)
#pragma unroll
                    for (int j = 0; j < 2; j++) {
                        const int n = nb + q * 8 + tig * 2 + j;
                        float raw = c[mi][q][r * 2 + j];
                        if (n == m) g_pos[m] = raw;            // predicated STG
                        float v = (n == m) ? -CUDART_INF_F : raw + MARGIN;
                        mm = fmaxf(mm, v);
                    }
#pragma unroll
                for (int d = 1; d <= 2; d <<= 1)
                    mm = fmaxf(mm, __shfl_xor_sync(0xffffffffu, mm, d));
                float ss = 0.f;
#pragma unroll
                for (int q = 0; q < 8; q++)
#pragma unroll
                    for (int j = 0; j < 2; j++) {
                        const int n = nb + q * 8 + tig * 2 + j;
                        float v = (n == m) ? -CUDART_INF_F : c[mi][q][r * 2 + j] + MARGIN;
                        ss += __expf(v * INV_L - mm * INV_L);
                    }
#pragma unroll
                for (int d = 1; d <= 2; d <<= 1)
                    ss += __shfl_xor_sync(0xffffffffu, ss, d);
                if (tig == 0)
                    rowp[(warp_m * 32 + mi * 16 + gID + 8 * r) * 2 + warp_n] = make_float2(mm, ss);
            }

        // cols (i2t)
#pragma unroll
        for (int q = 0; q < 8; q++)
#pragma unroll
            for (int j = 0; j < 2; j++) {
                const int n = nb + q * 8 + tig * 2 + j;
                float mm = -CUDART_INF_F;
#pragma unroll
                for (int mi = 0; mi < 2; mi++)
#pragma unroll
                    for (int r = 0; r < 2; r++) {
                        const int m = mb + mi * 16 + gID + 8 * r;
                        float v = (m == n) ? -CUDART_INF_F : c[mi][q][r * 2 + j] + MARGIN;
                        mm = fmaxf(mm, v);
                    }
#pragma unroll
                for (int d = 4; d <= 16; d <<= 1)
                    mm = fmaxf(mm, __shfl_xor_sync(0xffffffffu, mm, d));
                float ss = 0.f;
#pragma unroll
                for (int mi = 0; mi < 2; mi++)
#pragma unroll
                    for (int r = 0; r < 2; r++) {
                        const int m = mb + mi * 16 + gID + 8 * r;
                        float v = (m == n) ? -CUDART_INF_F : c[mi][q][r * 2 + j] + MARGIN;
                        ss += __expf(v * INV_L - mm * INV_L);
                    }
#pragma unroll
                for (int d = 4; d <= 16; d <<= 1)
                    ss += __shfl_xor_sync(0xffffffffu, ss, d);
                if (gID == 0)
                    colp[(warp_n * 64 + q * 8 + tig * 2 + j) * 4 + warp_m] = make_float2(mm, ss);
            }

        __syncthreads();
        if (tid < 128) {
            float2 a0 = rowp[tid * 2], a1 = rowp[tid * 2 + 1];
            float m = a0.x, s = a0.y;
            lse_merge(m, s, a1.x, a1.y);
            g_rowp[(size_t)(m0 + tid) * 32 + ntile] = make_float2(m, s);

            float2 q0 = colp[tid * 4], q1 = colp[tid * 4 + 1];
            float2 q2 = colp[tid * 4 + 2], q3 = colp[tid * 4 + 3];
            float cm = q0.x, cs = q0.y;
            lse_merge(cm, cs, q1.x, q1.y);
            lse_merge(cm, cs, q2.x, q2.y);
            lse_merge(cm, cs, q3.x, q3.y);
            g_colp[(size_t)(n0 + tid) * 32 + mtile] = make_float2(cm, cs);
        }

        // reset accumulators for next tile
#pragma unroll
        for (int i = 0; i < 2; i++)
#pragma unroll
            for (int j = 0; j < 8; j++)
#pragma unroll
                for (int k = 0; k < 4; k++) c[i][j][k] = 0.f;
    }
}

// ---------------------------------------------------------------------------
// Merge 32 partials per row / per col -> per-row losses. One warp per id.
// ---------------------------------------------------------------------------
__global__ void __launch_bounds__(256) merge_rowscols() {
    const int wid = threadIdx.x >> 5, lane = threadIdx.x & 31;
    const int id = blockIdx.x * 8 + wid;            // 0..8191
    float2 p = (id < B_DIM) ? g_rowp[(size_t)id * 32 + lane]
                            : g_colp[(size_t)(id - B_DIM) * 32 + lane];
    float m = p.x, s = p.y;
    float gm = m;
#pragma unroll
    for (int d = 16; d; d >>= 1)
        gm = fmaxf(gm, __shfl_xor_sync(0xffffffffu, gm, d));
    s *= __expf((m - gm) * INV_L);
#pragma unroll
    for (int d = 16; d; d >>= 1)
        s += __shfl_xor_sync(0xffffffffu, s, d);
    if (lane == 0) g_loss[id] = finish_loss(gm, s, g_pos[id & (B_DIM - 1)]);
}

__global__ void __launch_bounds__(512) final_reduce(float* __restrict__ out) {
    __shared__ double sh[512];
    const float4* L = (const float4*)g_loss;
    float4 v = L[threadIdx.x];
    float4 w = L[threadIdx.x + 512];
    float4 x = L[threadIdx.x + 1024];
    float4 y = L[threadIdx.x + 1536];
    sh[threadIdx.x] = (double)v.x + v.y + v.z + v.w + (double)w.x + w.y + w.z + w.w
                    + (double)x.x + x.y + x.z + x.w + (double)y.x + y.y + y.z + y.w;
    __syncthreads();
    for (int off = 256; off; off >>= 1) {
        if (threadIdx.x < off) sh[threadIdx.x] += sh[threadIdx.x + off];
        __syncthreads();
    }
    if (threadIdx.x == 0) out[0] = (float)(sh[0] / (2.0 * B_DIM));
}

// ---------------------------------------------------------------------------
extern "C" void kernel_launch(void* const* d_in, const int* in_sizes, int n_in,
                              void* d_out, int out_size) {
    const float* img = (const float*)d_in[0];
    const float* txt = (const float*)d_in[1];

    cudaFuncSetAttribute(gemm_lse, cudaFuncAttributeMaxDynamicSharedMemorySize, SMEM_TOTAL);

    convert_h<<<dim3(1024, 2), 256>>>(img, txt);
    gemm_lse<<<NCTA, 256, SMEM_TOTAL>>>();
    merge_rowscols<<<1024, 256>>>();
    final_reduce<<<1, 512>>>((float*)d_out);
}

// round 14
// speedup vs baseline: 1.0950x; 1.0950x over previous
#include <cuda_runtime.h>
#include <cuda_fp16.h>
#include <math_constants.h>
#include <cstdint>

// ============================================================================
// ContrastiveLoss: S = txt @ img^T once via single-pass fp16 mma.sync.
// Row-LSE (t2i) + Col-LSE (i2t) fused into the GEMM epilogue, branch-free
// two-pass form (R11 structure: 49.6us best).
// R14 = R11 with ONE change: convert_h at 2x threads (R12 profile showed it
// latency-bound at issue=8%, 6.0us; predict ~3.5us). Mainloop is at ~90% of
// the sm_100 legacy-HMMA pipe floor (R8/R9/R13 all neutral) — left alone.
// ============================================================================

#define B_DIM 4096
#define D_DIM 256
#define MARGIN 0.2f
#define INV_L  100.0f
#define SWZ(x) ((x) ^ (((x) >> 3) & 0x70))

__device__ __align__(16) __half g_txt_h[B_DIM * D_DIM];
__device__ __align__(16) __half g_img_h[B_DIM * D_DIM];
__device__ float2 g_rowp[B_DIM * 32];     // (row, ntile)
__device__ float2 g_colp[B_DIM * 32];     // (col, mtile)
__device__ float  g_pos[B_DIM];
__device__ float  g_loss[2 * B_DIM];

// ---- PTX helpers (sm_80-portable only) ----
__device__ __forceinline__ uint32_t smem_u32(const void* p) {
    uint32_t a;
    asm("{ .reg .u64 t; cvta.to.shared.u64 t, %1; cvt.u32.u64 %0, t; }" : "=r"(a) : "l"(p));
    return a;
}
__device__ __forceinline__ void cpa16(uint32_t dst, const void* src) {
    asm volatile("cp.async.cg.shared.global [%0], [%1], 16;" :: "r"(dst), "l"(src));
}
#define CP_COMMIT() asm volatile("cp.async.commit_group;" ::: "memory")
#define CP_WAIT(n)  asm volatile("cp.async.wait_group %0;" :: "n"(n) : "memory")

__device__ __forceinline__ void ldm4(uint32_t* r, uint32_t addr) {
    asm volatile("ldmatrix.sync.aligned.m8n8.x4.shared.b16 {%0,%1,%2,%3}, [%4];"
                 : "=r"(r[0]), "=r"(r[1]), "=r"(r[2]), "=r"(r[3]) : "r"(addr));
}
__device__ __forceinline__ void mma_f16(float* c, const uint32_t* a, uint32_t b0, uint32_t b1) {
    asm volatile("mma.sync.aligned.m16n8k16.row.col.f32.f16.f16.f32 "
                 "{%0,%1,%2,%3}, {%4,%5,%6,%7}, {%8,%9}, {%0,%1,%2,%3};"
                 : "+f"(c[0]), "+f"(c[1]), "+f"(c[2]), "+f"(c[3])
                 : "r"(a[0]), "r"(a[1]), "r"(a[2]), "r"(a[3]), "r"(b0), "r"(b1));
}

__device__ __forceinline__ void lse_merge(float& m, float& s, float m2, float s2) {
    if (m2 > m) { s = s * __expf((m - m2) * INV_L) + s2; m = m2; }
    else if (s2 > 0.f) s += s2 * __expf((m2 - m) * INV_L);
}
__device__ __forceinline__ float finish_loss(float m, float s, float pos) {
    float M = fmaxf(m, pos);
    float tot = __expf((pos - M) * INV_L) + s * __expf((m - M) * INV_L);
    return (M - pos) * INV_L + logf(tot);
}

// ---------------------------------------------------------------------------
// Convert fp32 -> fp16 plane, row-major. 1 thread = 4 elements (2x threads
// vs R11: kernel measured latency-bound at issue=8%).
// ---------------------------------------------------------------------------
__global__ void __launch_bounds__(256) convert_h(const float* __restrict__ img,
                                                 const float* __restrict__ txt) {
    const float* src = (blockIdx.y == 0) ? img : txt;
    char* dst = (char*)((blockIdx.y == 0) ? g_img_h : g_txt_h);
    int idx = blockIdx.x * 256 + threadIdx.x;          // 0..262143
    size_t e0 = (size_t)idx * 4;
    float4 a = *(const float4*)(src + e0);
    union { __half h[4]; uint2 u; } H;
    H.h[0] = __float2half_rn(a.x);
    H.h[1] = __float2half_rn(a.y);
    H.h[2] = __float2half_rn(a.z);
    H.h[3] = __float2half_rn(a.w);
    *(uint2*)(dst + e0 * 2) = H.u;
}

// ---------------------------------------------------------------------------
// GEMM + fused row/col LSE. CTA tile 128x128, 8 warps = 4(M) x 2(N),
// warp tile 32x64. K: 8 chunks of 32; 4-stage cp.async circular pipeline.
// Stage = A(8KB) + B(8KB) = 16KB; 4 stages + pad = 66KB -> 2 CTAs/SM.
// ---------------------------------------------------------------------------
#define STAGE 16384
#define A_OFF 0
#define B_OFF 8192
#define SMEM_TOTAL (4 * STAGE + 1024)

__device__ __forceinline__ void load_mat(uint32_t dst, const char* src, int row0, int s, int tid) {
#pragma unroll
    for (int it = 0; it < 2; it++) {
        int idx = it * 256 + tid;
        int r = idx >> 2, u = idx & 3;
        uint32_t off = (uint32_t)(r * 64 + u * 16);
        cpa16(dst + SWZ(off), src + (size_t)(row0 + r) * 512 + s * 64 + u * 16);
    }
}

__global__ void __launch_bounds__(256, 2) gemm_lse() {
    extern __shared__ char smem[];
    const uint32_t sb = (smem_u32(smem) + 1023) & ~1023u;

    const int tid = threadIdx.x, lane = tid & 31, wid = tid >> 5;
    const int warp_m = wid & 3, warp_n = wid >> 2;
    const int ntile = blockIdx.x, mtile = blockIdx.y;
    const int m0 = mtile * 128, n0 = ntile * 128;

    const char* At = (const char*)g_txt_h;
    const char* Bi = (const char*)g_img_h;

    float c[2][8][4];
#pragma unroll
    for (int i = 0; i < 2; i++)
#pragma unroll
        for (int j = 0; j < 8; j++)
#pragma unroll
            for (int k = 0; k < 4; k++) c[i][j][k] = 0.f;

    const int a_row = warp_m * 32 + (lane & 15);
    const int a_kb  = (lane >> 4) << 4;
    const int b_row = warp_n * 64 + (lane & 7) + ((lane >> 4) << 3);
    const int b_kb  = ((lane >> 3) & 1) << 4;

    // prologue: stages 0..2 (3 groups in flight)
#pragma unroll
    for (int s = 0; s < 3; s++) {
        uint32_t bb = sb + s * STAGE;
        load_mat(bb + A_OFF, At, m0, s, tid);
        load_mat(bb + B_OFF, Bi, n0, s, tid);
        CP_COMMIT();
    }

#pragma unroll
    for (int s = 0; s < 8; s++) {
        if (s <= 5) CP_WAIT(2);
        else if (s == 6) CP_WAIT(1);
        else CP_WAIT(0);
        __syncthreads();

        if (s + 3 < 8) {
            uint32_t bb2 = sb + ((s + 3) & 3) * STAGE;
            load_mat(bb2 + A_OFF, At, m0, s + 3, tid);
            load_mat(bb2 + B_OFF, Bi, n0, s + 3, tid);
            CP_COMMIT();
        }

        const uint32_t bb = sb + (s & 3) * STAGE;
#pragma unroll
        for (int ks = 0; ks < 2; ks++) {
            const int kb = ks * 32;
            uint32_t ah[2][4];
#pragma unroll
            for (int mi = 0; mi < 2; mi++)
                ldm4(ah[mi], bb + A_OFF + SWZ((uint32_t)((a_row + mi * 16) * 64 + kb + a_kb)));
            uint32_t bh[4][4];
#pragma unroll
            for (int p = 0; p < 4; p++)
                ldm4(bh[p], bb + B_OFF + SWZ((uint32_t)((b_row + p * 16) * 64 + kb + b_kb)));
#pragma unroll
            for (int mi = 0; mi < 2; mi++)
#pragma unroll
                for (int p = 0; p < 4; p++)
#pragma unroll
                    for (int h = 0; h < 2; h++)
                        mma_f16(c[mi][p * 2 + h], ah[mi], bh[p][h * 2], bh[p][h * 2 + 1]);
        }
    }
    __syncthreads();

    // ---- epilogue: BRANCH-FREE two-pass LSE ----
    const int gID = lane >> 2, tig = lane & 3;
    const int mb = m0 + warp_m * 32;
    const int nb = n0 + warp_n * 64;

    float2* rowp = (float2*)smem;              // [128][2]
    float2* colp = (float2*)(smem + 2048);     // [128][4]

    // rows (t2i): 4 rows/thread x 16 cols; quad shfl max+sum
#pragma unroll
    for (int mi = 0; mi < 2; mi++)
#pragma unroll
        for (int r = 0; r < 2; r++) {
            const int m = mb + mi * 16 + gID + 8 * r;
            float mm = -CUDART_INF_F;
#pragma unroll
            for (int q = 0; q < 8; q++)
#pragma unroll
                for (int j = 0; j < 2; j++) {
                    const int n = nb + q * 8 + tig * 2 + j;
                    float raw = c[mi][q][r * 2 + j];
                    if (n == m) g_pos[m] = raw;                // predicated STG
                    float v = (n == m) ? -CUDART_INF_F : raw + MARGIN;
                    mm = fmaxf(mm, v);
                }
#pragma unroll
            for (int d = 1; d <= 2; d <<= 1)
                mm = fmaxf(mm, __shfl_xor_sync(0xffffffffu, mm, d));
            float ss = 0.f;
#pragma unroll
            for (int q = 0; q < 8; q++)
#pragma unroll
                for (int j = 0; j < 2; j++) {
                    const int n = nb + q * 8 + tig * 2 + j;
                    float v = (n == m) ? -CUDART_INF_F : c[mi][q][r * 2 + j] + MARGIN;
                    ss += __expf(v * INV_L - mm * INV_L);
                }
#pragma unroll
            for (int d = 1; d <= 2; d <<= 1)
                ss += __shfl_xor_sync(0xffffffffu, ss, d);
            if (tig == 0)
                rowp[(warp_m * 32 + mi * 16 + gID + 8 * r) * 2 + warp_n] = make_float2(mm, ss);
        }

    // cols (i2t): 16 cols/thread x 4 rows; gID-direction shfl max+sum
#pragma unroll
    for (int q = 0; q < 8; q++)
#pragma unroll
        for (int j = 0; j < 2; j++) {
            const int n = nb + q * 8 + tig * 2 + j;
            float mm = -CUDART_INF_F;
#pragma unroll
            for (int mi = 0; mi < 2; mi++)
#pragma unroll
                for (int r = 0; r < 2; r++) {
                    const int m = mb + mi * 16 + gID + 8 * r;
                    float v = (m == n) ? -CUDART_INF_F : c[mi][q][r * 2 + j] + MARGIN;
                    mm = fmaxf(mm, v);
                }
#pragma unroll
            for (int d = 4; d <= 16; d <<= 1)
                mm = fmaxf(mm, __shfl_xor_sync(0xffffffffu, mm, d));
            float ss = 0.f;
#pragma unroll
            for (int mi = 0; mi < 2; mi++)
#pragma unroll
                for (int r = 0; r < 2; r++) {
                    const int m = mb + mi * 16 + gID + 8 * r;
                    float v = (m == n) ? -CUDART_INF_F : c[mi][q][r * 2 + j] + MARGIN;
                    ss += __expf(v * INV_L - mm * INV_L);
                }
#pragma unroll
            for (int d = 4; d <= 16; d <<= 1)
                ss += __shfl_xor_sync(0xffffffffu, ss, d);
            if (gID == 0)
                colp[(warp_n * 64 + q * 8 + tig * 2 + j) * 4 + warp_m] = make_float2(mm, ss);
        }

    __syncthreads();
    if (tid < 128) {
        float2 a0 = rowp[tid * 2], a1 = rowp[tid * 2 + 1];
        float m = a0.x, s = a0.y;
        lse_merge(m, s, a1.x, a1.y);
        g_rowp[(size_t)(m0 + tid) * 32 + ntile] = make_float2(m, s);

        float2 q0 = colp[tid * 4], q1 = colp[tid * 4 + 1];
        float2 q2 = colp[tid * 4 + 2], q3 = colp[tid * 4 + 3];
        float cm = q0.x, cs = q0.y;
        lse_merge(cm, cs, q1.x, q1.y);
        lse_merge(cm, cs, q2.x, q2.y);
        lse_merge(cm, cs, q3.x, q3.y);
        g_colp[(size_t)(n0 + tid) * 32 + mtile] = make_float2(cm, cs);
    }
}

// ---------------------------------------------------------------------------
// Merge 32 partials per row / per col -> per-row losses. One warp per id.
// ---------------------------------------------------------------------------
__global__ void __launch_bounds__(256) merge_rowscols() {
    const int wid = threadIdx.x >> 5, lane = threadIdx.x & 31;
    const int id = blockIdx.x * 8 + wid;            // 0..8191
    float2 p = (id < B_DIM) ? g_rowp[(size_t)id * 32 + lane]
                            : g_colp[(size_t)(id - B_DIM) * 32 + lane];
    // branch-free warp merge: global max first, then rescaled sums
    float m = p.x, s = p.y;
    float gm = m;
#pragma unroll
    for (int d = 16; d; d >>= 1)
        gm = fmaxf(gm, __shfl_xor_sync(0xffffffffu, gm, d));
    s *= __expf((m - gm) * INV_L);
#pragma unroll
    for (int d = 16; d; d >>= 1)
        s += __shfl_xor_sync(0xffffffffu, s, d);
    if (lane == 0) g_loss[id] = finish_loss(gm, s, g_pos[id & (B_DIM - 1)]);
}

__global__ void __launch_bounds__(512) final_reduce(float* __restrict__ out) {
    __shared__ double sh[512];
    const float4* L = (const float4*)g_loss;
    float4 v = L[threadIdx.x];
    float4 w = L[threadIdx.x + 512];
    float4 x = L[threadIdx.x + 1024];
    float4 y = L[threadIdx.x + 1536];
    sh[threadIdx.x] = (double)v.x + v.y + v.z + v.w + (double)w.x + w.y + w.z + w.w
                    + (double)x.x + x.y + x.z + x.w + (double)y.x + y.y + y.z + y.w;
    __syncthreads();
    for (int off = 256; off; off >>= 1) {
        if (threadIdx.x < off) sh[threadIdx.x] += sh[threadIdx.x + off];
        __syncthreads();
    }
    if (threadIdx.x == 0) out[0] = (float)(sh[0] / (2.0 * B_DIM));
}

// ---------------------------------------------------------------------------
extern "C" void kernel_launch(void* const* d_in, const int* in_sizes, int n_in,
                              void* d_out, int out_size) {
    const float* img = (const float*)d_in[0];
    const float* txt = (const float*)d_in[1];

    cudaFuncSetAttribute(gemm_lse, cudaFuncAttributeMaxDynamicSharedMemorySize, SMEM_TOTAL);

    convert_h<<<dim3(1024, 2), 256>>>(img, txt);
    gemm_lse<<<dim3(32, 32), 256, SMEM_TOTAL>>>();
    merge_rowscols<<<1024, 256>>>();
    final_reduce<<<1, 512>>>((float*)d_out);
}